// round 13
// baseline (speedup 1.0000x reference)
#include <cuda_runtime.h>
#include <cuda_fp16.h>
#include <cstdint>

// ============================================================================
// BinaryDense: out[8192,2048] = X[8192,2048] @ (W >= 0 ? 1 : 0)[2048,2048]
// Plain sm_100 target (no tcgen05). fp16 mma.sync HMMA GEMM, fp32 accum.
// R13: kill the 15.6% tail-wave loss. Tile 128x64 -> 2048 CTAs on 296
// slots = 6.92 waves (tail ~1.1%), full K per CTA, plain STG epilogue.
// 4 warps (2x2, 64x32 warp tiles), STAGES=4 (24KB stages), 2 CTAs/SM.
// ============================================================================

#define B_DIM 8192
#define K_DIM 2048
#define N_DIM 2048

#define BM 128
#define BN 64
#define BK 64
#define STAGES 4
#define KTILES (K_DIM / BK)          // 32

#define A_STAGE_BYTES (BM * BK * 2)  // 16384
#define B_STAGE_BYTES (BN * BK * 2)  // 8192
#define STAGE_BYTES (A_STAGE_BYTES + B_STAGE_BYTES)  // 24576
#define SMEM_TOTAL (STAGES * STAGE_BYTES)            // 98304 (x2 CTA = 192K)

#define CONVERT_BLOCKS 8192          // X: 8192*2048 / (256*8)
#define BIN_BLOCKS (64 * 64)         // W 32x32 tiles

// Scratch: fp16 X and binarized+transposed W (Wb is [N, K], K contiguous)
__device__ __align__(1024) __half g_Xh[(size_t)B_DIM * K_DIM];
__device__ __align__(1024) __half g_Wb[(size_t)N_DIM * K_DIM];

// ---------------------------------------------------------------------------
__device__ __forceinline__ uint32_t smem_u32(const void* p) {
    uint32_t a;
    asm("{ .reg .u64 t; cvta.to.shared.u64 t, %1; cvt.u32.u64 %0, t; }"
        : "=r"(a) : "l"(p));
    return a;
}

__device__ __forceinline__ void cp_async16(uint32_t dst, const void* src) {
    asm volatile("cp.async.cg.shared.global [%0], [%1], 16;"
                 :: "r"(dst), "l"(src) : "memory");
}
__device__ __forceinline__ void cp_commit() {
    asm volatile("cp.async.commit_group;" ::: "memory");
}
template <int N>
__device__ __forceinline__ void cp_wait() {
    asm volatile("cp.async.wait_group %0;" :: "n"(N) : "memory");
}

__device__ __forceinline__ void ldsm_x4(uint32_t& r0, uint32_t& r1,
                                        uint32_t& r2, uint32_t& r3, uint32_t a) {
    asm volatile("ldmatrix.sync.aligned.m8n8.x4.shared.b16 {%0,%1,%2,%3}, [%4];"
                 : "=r"(r0), "=r"(r1), "=r"(r2), "=r"(r3) : "r"(a));
}

__device__ __forceinline__ void mma16816(float* d, const uint32_t* a,
                                         const uint32_t* b) {
    asm volatile(
        "mma.sync.aligned.m16n8k16.row.col.f32.f16.f16.f32 "
        "{%0,%1,%2,%3}, {%4,%5,%6,%7}, {%8,%9}, {%0,%1,%2,%3};"
        : "+f"(d[0]), "+f"(d[1]), "+f"(d[2]), "+f"(d[3])
        : "r"(a[0]), "r"(a[1]), "r"(a[2]), "r"(a[3]), "r"(b[0]), "r"(b[1]));
}

// ---------------------------------------------------------------------------
// Prep kernel (merged): blocks [0, CONVERT_BLOCKS) convert X fp32->fp16;
// blocks [CONVERT_BLOCKS, +BIN_BLOCKS) binarize+transpose W -> Wb[N,K] fp16.
// ---------------------------------------------------------------------------
__global__ void __launch_bounds__(256) prep_kernel(
    const float* __restrict__ x, const float* __restrict__ w,
    __half* __restrict__ xh, __half* __restrict__ wb) {
    int bid = blockIdx.x;
    int tid = threadIdx.x;
    if (bid < CONVERT_BLOCKS) {
        size_t i = ((size_t)bid * 256 + tid) * 8;
        float4 v0 = *reinterpret_cast<const float4*>(x + i);
        float4 v1 = *reinterpret_cast<const float4*>(x + i + 4);
        union { __half2 h[4]; uint4 u; } pk;
        pk.h[0] = __floats2half2_rn(v0.x, v0.y);
        pk.h[1] = __floats2half2_rn(v0.z, v0.w);
        pk.h[2] = __floats2half2_rn(v1.x, v1.y);
        pk.h[3] = __floats2half2_rn(v1.z, v1.w);
        *reinterpret_cast<uint4*>(xh + i) = pk.u;
    } else {
        __shared__ __half tile[32][33];
        int b = bid - CONVERT_BLOCKS;
        int n0 = (b & 63) * 32, k0 = (b >> 6) * 32;
        int tx = tid & 31, ty = tid >> 5;
#pragma unroll
        for (int r = 0; r < 32; r += 8) {
            float v = w[(size_t)(k0 + ty + r) * N_DIM + n0 + tx];
            tile[ty + r][tx] = __float2half(v < 0.0f ? 0.0f : 1.0f);
        }
        __syncthreads();
#pragma unroll
        for (int r = 0; r < 32; r += 8) {
            wb[(size_t)(n0 + ty + r) * K_DIM + k0 + tx] = tile[tx][ty + r];
        }
    }
}

// ---------------------------------------------------------------------------
// GEMM: 128x64 block tile, BK=64, 4-stage cp.async, 2 CTAs/SM.
// 128 threads = 4 warps (2 M x 2 N), 64x32 warp tiles, 64 fp32 acc/thread.
// One __syncthreads per iteration. Grid 32x64 = 2048 CTAs -> 6.92 waves.
// Smem rows 128 B (64 halfs); SW128 swizzle: 16B-chunk ^= (row & 7).
// ---------------------------------------------------------------------------
__global__ void __launch_bounds__(128, 2)
bingemm_kernel(const __half* __restrict__ Xh, const __half* __restrict__ Wb,
               float* __restrict__ out) {
    extern __shared__ char smem[];
    const uint32_t sb = smem_u32(smem);

    const int tid = threadIdx.x;
    const int lane = tid & 31;
    const int wid = tid >> 5;          // 0..3
    const int wm = (wid >> 1) * 64;    // warp M offset (2 rows of warps)
    const int wn = (wid & 1) * 32;     // warp N offset (2 cols of warps)

    const int mBase = blockIdx.y * BM;
    const int nBase = blockIdx.x * BN;

    // ---- cp.async precompute: 12 loads/thread/iter (8 A + 4 B) ---------
    // 128 threads cover 16 rows x 8 chunks per pass; (row & 7) invariant
    // across passes (stride 16) so addresses are base + constant offsets.
    const int row0 = tid >> 3;              // 0..15
    const int chunk = tid & 7;
    const uint32_t sw = (uint32_t)(chunk ^ (row0 & 7)) * 16;
    const uint32_t dA0 = (uint32_t)row0 * 128 + sw;
    const uint32_t dB0 = A_STAGE_BYTES + dA0;
    const __half* gA = Xh + (size_t)(mBase + row0) * K_DIM + chunk * 8;
    const __half* gB = Wb + (size_t)(nBase + row0) * K_DIM + chunk * 8;

    // ---- ldmatrix addresses (stage-relative; k16 step s => XOR s<<5) ---
    uint32_t aAddr[4];
#pragma unroll
    for (int mi = 0; mi < 4; ++mi) {
        int r = wm + mi * 16 + (lane & 15);
        int kc0 = lane >> 4;
        aAddr[mi] = (uint32_t)(r * 128 + ((kc0 ^ (r & 7)) * 16));
    }
    uint32_t bAddr[2];
#pragma unroll
    for (int j = 0; j < 2; ++j) {
        int r = wn + j * 16 + (lane & 7) + ((lane >> 4) & 1) * 8;
        int kc0 = (lane >> 3) & 1;
        bAddr[j] = (uint32_t)(A_STAGE_BYTES + r * 128 + ((kc0 ^ (r & 7)) * 16));
    }

    float acc[4][4][4];
#pragma unroll
    for (int mi = 0; mi < 4; ++mi)
#pragma unroll
        for (int ni = 0; ni < 4; ++ni)
#pragma unroll
            for (int e = 0; e < 4; ++e) acc[mi][ni][e] = 0.0f;

    // ---- prologue: fill STAGES-1 = 3 stages ----------------------------
#pragma unroll
    for (int s = 0; s < STAGES - 1; ++s) {
        uint32_t st = sb + s * STAGE_BYTES;
        int kOff = s * BK;
#pragma unroll
        for (int p = 0; p < 8; ++p)
            cp_async16(st + dA0 + p * (16 * 128),
                       gA + (size_t)(16 * p) * K_DIM + kOff);
#pragma unroll
        for (int p = 0; p < 4; ++p)
            cp_async16(st + dB0 + p * (16 * 128),
                       gB + (size_t)(16 * p) * K_DIM + kOff);
        cp_commit();
    }

    // ---- mainloop: one __syncthreads per BK=64 iteration ---------------
    // Iter it reads slot it%4; prefetch writes slot (it+3)%4 = slot read
    // at it-1, freed by the sync at the top of iter it.
    int ldSlot = 0, pfSlot = STAGES - 1;
    for (int it = 0; it < KTILES; ++it) {
        cp_wait<STAGES - 2>();   // stage `it` resident (own groups)
        __syncthreads();         // cross-thread completion + stage it-1 free

        int pf = it + STAGES - 1;
        if (pf < KTILES) {
            uint32_t st = sb + pfSlot * STAGE_BYTES;
            int kOff = pf * BK;
#pragma unroll
            for (int p = 0; p < 8; ++p)
                cp_async16(st + dA0 + p * (16 * 128),
                           gA + (size_t)(16 * p) * K_DIM + kOff);
#pragma unroll
            for (int p = 0; p < 4; ++p)
                cp_async16(st + dB0 + p * (16 * 128),
                           gB + (size_t)(16 * p) * K_DIM + kOff);
        }
        cp_commit();

        uint32_t stage = sb + ldSlot * STAGE_BYTES;
#pragma unroll
        for (int s = 0; s < 4; ++s) {       // four k16 steps per BK=64
            const uint32_t kx = (uint32_t)s << 5;   // XOR: chunk bits 1-2
            uint32_t a[4][4];
#pragma unroll
            for (int mi = 0; mi < 4; ++mi)
                ldsm_x4(a[mi][0], a[mi][1], a[mi][2], a[mi][3],
                        stage + (aAddr[mi] ^ kx));
            uint32_t b[2][4];
#pragma unroll
            for (int j = 0; j < 2; ++j)
                ldsm_x4(b[j][0], b[j][1], b[j][2], b[j][3],
                        stage + (bAddr[j] ^ kx));
#pragma unroll
            for (int mi = 0; mi < 4; ++mi)
#pragma unroll
                for (int ni = 0; ni < 4; ++ni)
                    mma16816(acc[mi][ni], a[mi], &b[ni >> 1][(ni & 1) * 2]);
        }

        if (++ldSlot == STAGES) ldSlot = 0;
        if (++pfSlot == STAGES) pfSlot = 0;
    }

    // ---- epilogue: direct float2 stores --------------------------------
#pragma unroll
    for (int mi = 0; mi < 4; ++mi) {
#pragma unroll
        for (int h = 0; h < 2; ++h) {
            size_t row = (size_t)(mBase + wm + mi * 16 + h * 8 + (lane >> 2));
            float* p = out + row * N_DIM + nBase + wn + (lane & 3) * 2;
#pragma unroll
            for (int ni = 0; ni < 4; ++ni) {
                float2 v = make_float2(acc[mi][ni][2 * h], acc[mi][ni][2 * h + 1]);
                *reinterpret_cast<float2*>(p + ni * 8) = v;
            }
        }
    }
}

// ---------------------------------------------------------------------------
extern "C" void kernel_launch(void* const* d_in, const int* in_sizes, int n_in,
                              void* d_out, int out_size) {
    const float* x = (const float*)d_in[0];   // [8192, 2048] fp32
    const float* w = (const float*)d_in[1];   // [2048, 2048] fp32
    float* out = (float*)d_out;               // [8192, 2048] fp32

    void *xh_ptr = nullptr, *wb_ptr = nullptr;
    cudaGetSymbolAddress(&xh_ptr, g_Xh);
    cudaGetSymbolAddress(&wb_ptr, g_Wb);

    prep_kernel<<<CONVERT_BLOCKS + BIN_BLOCKS, 256>>>(
        x, w, (__half*)xh_ptr, (__half*)wb_ptr);

    cudaFuncSetAttribute(bingemm_kernel,
                         cudaFuncAttributeMaxDynamicSharedMemorySize, SMEM_TOTAL);
    bingemm_kernel<<<dim3(N_DIM / BN, B_DIM / BM), 128, SMEM_TOTAL>>>(
        (const __half*)xh_ptr, (const __half*)wb_ptr, out);
}

// round 16
// speedup vs baseline: 1.0290x; 1.0290x over previous
#include <cuda_runtime.h>
#include <cuda_fp16.h>
#include <cstdint>

// ============================================================================
// BinaryDense: out[8192,2048] = X[8192,2048] @ (W >= 0 ? 1 : 0)[2048,2048]
// Plain sm_100 target (no tcgen05). fp16 mma.sync HMMA GEMM, fp32 accum.
// R16 = R14 resubmit, attempt 3 (R14/R15 were container-acquisition
// failures; kernel never executed — audited clean for hang/OOB).
// Maximize compute per synchronization point. Measured law:
// eta_inloop ~= C/(C+280cyc) where C = tensor-cycles per iteration.
// BK=128 (two BK=64 sub-blocks per stage), 128x128 tile, STAGES=3,
// 1 CTA/SM (192KB smem), 256 thr / 8 warps (R4 compute core).
// 16 iters x 4096 tensor-cyc/iter; grid 1024 -> 6.92 waves (tail ~1%).
// ============================================================================

#define B_DIM 8192
#define K_DIM 2048
#define N_DIM 2048

#define BM 128
#define BN 128
#define BK 128
#define STAGES 3
#define KTILES (K_DIM / BK)          // 16

#define SUB_BYTES 16384              // one 128-row x 128B SW128 sub-block
#define A_OFF 0                      // A sub0 @0, A sub1 @16384
#define B_OFF 32768                  // B sub0 @32768, B sub1 @49152
#define STAGE_BYTES 65536
#define SMEM_TOTAL (STAGES * STAGE_BYTES)   // 196608 -> 1 CTA/SM

#define CONVERT_BLOCKS 8192          // X: 8192*2048 / (256*8)
#define BIN_BLOCKS (64 * 64)         // W 32x32 tiles

// Scratch: fp16 X and binarized+transposed W (Wb is [N, K], K contiguous)
__device__ __align__(1024) __half g_Xh[(size_t)B_DIM * K_DIM];
__device__ __align__(1024) __half g_Wb[(size_t)N_DIM * K_DIM];

// ---------------------------------------------------------------------------
__device__ __forceinline__ uint32_t smem_u32(const void* p) {
    uint32_t a;
    asm("{ .reg .u64 t; cvta.to.shared.u64 t, %1; cvt.u32.u64 %0, t; }"
        : "=r"(a) : "l"(p));
    return a;
}

__device__ __forceinline__ void cp_async16(uint32_t dst, const void* src) {
    asm volatile("cp.async.cg.shared.global [%0], [%1], 16;"
                 :: "r"(dst), "l"(src) : "memory");
}
__device__ __forceinline__ void cp_commit() {
    asm volatile("cp.async.commit_group;" ::: "memory");
}
template <int N>
__device__ __forceinline__ void cp_wait() {
    asm volatile("cp.async.wait_group %0;" :: "n"(N) : "memory");
}

__device__ __forceinline__ void ldsm_x4(uint32_t& r0, uint32_t& r1,
                                        uint32_t& r2, uint32_t& r3, uint32_t a) {
    asm volatile("ldmatrix.sync.aligned.m8n8.x4.shared.b16 {%0,%1,%2,%3}, [%4];"
                 : "=r"(r0), "=r"(r1), "=r"(r2), "=r"(r3) : "r"(a));
}

__device__ __forceinline__ void mma16816(float* d, const uint32_t* a,
                                         const uint32_t* b) {
    asm volatile(
        "mma.sync.aligned.m16n8k16.row.col.f32.f16.f16.f32 "
        "{%0,%1,%2,%3}, {%4,%5,%6,%7}, {%8,%9}, {%0,%1,%2,%3};"
        : "+f"(d[0]), "+f"(d[1]), "+f"(d[2]), "+f"(d[3])
        : "r"(a[0]), "r"(a[1]), "r"(a[2]), "r"(a[3]), "r"(b[0]), "r"(b[1]));
}

// ---------------------------------------------------------------------------
// Prep kernel (merged): blocks [0, CONVERT_BLOCKS) convert X fp32->fp16;
// blocks [CONVERT_BLOCKS, +BIN_BLOCKS) binarize+transpose W -> Wb[N,K] fp16.
// ---------------------------------------------------------------------------
__global__ void __launch_bounds__(256) prep_kernel(
    const float* __restrict__ x, const float* __restrict__ w,
    __half* __restrict__ xh, __half* __restrict__ wb) {
    int bid = blockIdx.x;
    int tid = threadIdx.x;
    if (bid < CONVERT_BLOCKS) {
        size_t i = ((size_t)bid * 256 + tid) * 8;
        float4 v0 = *reinterpret_cast<const float4*>(x + i);
        float4 v1 = *reinterpret_cast<const float4*>(x + i + 4);
        union { __half2 h[4]; uint4 u; } pk;
        pk.h[0] = __floats2half2_rn(v0.x, v0.y);
        pk.h[1] = __floats2half2_rn(v0.z, v0.w);
        pk.h[2] = __floats2half2_rn(v1.x, v1.y);
        pk.h[3] = __floats2half2_rn(v1.z, v1.w);
        *reinterpret_cast<uint4*>(xh + i) = pk.u;
    } else {
        __shared__ __half tile[32][33];
        int b = bid - CONVERT_BLOCKS;
        int n0 = (b & 63) * 32, k0 = (b >> 6) * 32;
        int tx = tid & 31, ty = tid >> 5;
#pragma unroll
        for (int r = 0; r < 32; r += 8) {
            float v = w[(size_t)(k0 + ty + r) * N_DIM + n0 + tx];
            tile[ty + r][tx] = __float2half(v < 0.0f ? 0.0f : 1.0f);
        }
        __syncthreads();
#pragma unroll
        for (int r = 0; r < 32; r += 8) {
            wb[(size_t)(n0 + ty + r) * K_DIM + k0 + tx] = tile[tx][ty + r];
        }
    }
}

// ---------------------------------------------------------------------------
// GEMM: 128x128 tile, BK=128 (2 x BK=64 sub-blocks), 3-stage cp.async,
// 1 CTA/SM. 256 threads = 8 warps (2 M x 4 N), 64x32 warp tiles.
// One __syncthreads per iteration (16 total), 8 k16-steps per iteration.
// Sub-block layout: A0@0 A1@16K B0@32K B1@48K; rows 128B, SW128 swizzle.
// ---------------------------------------------------------------------------
__global__ void __launch_bounds__(256, 1)
bingemm_kernel(const __half* __restrict__ Xh, const __half* __restrict__ Wb,
               float* __restrict__ out) {
    extern __shared__ char smem[];
    const uint32_t sb = smem_u32(smem);

    const int tid = threadIdx.x;
    const int lane = tid & 31;
    const int wid = tid >> 5;
    const int wm = (wid >> 2) * 64;   // warp M offset (2 rows of warps)
    const int wn = (wid & 3) * 32;    // warp N offset (4 cols of warps)

    const int mBase = blockIdx.y * BM;
    const int nBase = blockIdx.x * BN;

    // ---- cp.async precompute: 16 loads/thread/iter (8 A + 8 B) ---------
    // 256 threads cover 32 rows x 8 chunks per pass; 4 passes per sub.
    // (row & 7) invariant across passes (stride 32) -> constant offsets.
    const int row0 = tid >> 3;              // 0..31
    const int chunk = tid & 7;
    const uint32_t sw = (uint32_t)(chunk ^ (row0 & 7)) * 16;
    const uint32_t dA0 = (uint32_t)row0 * 128 + sw;          // + p*4096 + sub*16K
    const __half* gA = Xh + (size_t)(mBase + row0) * K_DIM + chunk * 8;
    const __half* gB = Wb + (size_t)(nBase + row0) * K_DIM + chunk * 8;

    // ---- ldmatrix addresses (sub-relative; k16 step ks => XOR ks<<5) ---
    uint32_t aAddr[4];
#pragma unroll
    for (int mi = 0; mi < 4; ++mi) {
        int r = wm + mi * 16 + (lane & 15);
        int kc0 = lane >> 4;
        aAddr[mi] = (uint32_t)(r * 128 + ((kc0 ^ (r & 7)) * 16));
    }
    uint32_t bAddr[2];
#pragma unroll
    for (int j = 0; j < 2; ++j) {
        int r = wn + j * 16 + (lane & 7) + ((lane >> 4) & 1) * 8;
        int kc0 = (lane >> 3) & 1;
        bAddr[j] = (uint32_t)(B_OFF + r * 128 + ((kc0 ^ (r & 7)) * 16));
    }

    float acc[4][4][4];
#pragma unroll
    for (int mi = 0; mi < 4; ++mi)
#pragma unroll
        for (int ni = 0; ni < 4; ++ni)
#pragma unroll
            for (int e = 0; e < 4; ++e) acc[mi][ni][e] = 0.0f;

    // ---- prologue: fill STAGES-1 = 2 stages ----------------------------
#pragma unroll
    for (int s = 0; s < STAGES - 1; ++s) {
        uint32_t st = sb + s * STAGE_BYTES;
#pragma unroll
        for (int sub = 0; sub < 2; ++sub) {
            int kOff = s * BK + sub * 64;
#pragma unroll
            for (int p = 0; p < 4; ++p) {
                cp_async16(st + A_OFF + sub * SUB_BYTES + dA0 + p * 4096,
                           gA + (size_t)(32 * p) * K_DIM + kOff);
                cp_async16(st + B_OFF + sub * SUB_BYTES + dA0 + p * 4096,
                           gB + (size_t)(32 * p) * K_DIM + kOff);
            }
        }
        cp_commit();
    }

    // ---- mainloop: one __syncthreads per BK=128 iteration (16) ---------
    int ldSlot = 0, pfSlot = STAGES - 1;
    for (int it = 0; it < KTILES; ++it) {
        cp_wait<STAGES - 2>();   // stage `it` resident (own groups)
        __syncthreads();         // cross-thread completion + stage it-1 free

        int pf = it + STAGES - 1;
        if (pf < KTILES) {       // prefetch into the slot freed by it-1
            uint32_t st = sb + pfSlot * STAGE_BYTES;
#pragma unroll
            for (int sub = 0; sub < 2; ++sub) {
                int kOff = pf * BK + sub * 64;
#pragma unroll
                for (int p = 0; p < 4; ++p) {
                    cp_async16(st + A_OFF + sub * SUB_BYTES + dA0 + p * 4096,
                               gA + (size_t)(32 * p) * K_DIM + kOff);
                    cp_async16(st + B_OFF + sub * SUB_BYTES + dA0 + p * 4096,
                               gB + (size_t)(32 * p) * K_DIM + kOff);
                }
            }
        }
        cp_commit();

        uint32_t stage = sb + ldSlot * STAGE_BYTES;
#pragma unroll
        for (int s = 0; s < 8; ++s) {       // eight k16 steps per BK=128
            const uint32_t subOff = (uint32_t)(s >> 2) * SUB_BYTES;
            const uint32_t kx = (uint32_t)(s & 3) << 5;  // chunk bits 1-2
            uint32_t a[4][4];
#pragma unroll
            for (int mi = 0; mi < 4; ++mi)
                ldsm_x4(a[mi][0], a[mi][1], a[mi][2], a[mi][3],
                        stage + subOff + (aAddr[mi] ^ kx));
            uint32_t b[2][4];
#pragma unroll
            for (int j = 0; j < 2; ++j)
                ldsm_x4(b[j][0], b[j][1], b[j][2], b[j][3],
                        stage + subOff + (bAddr[j] ^ kx));
#pragma unroll
            for (int mi = 0; mi < 4; ++mi)
#pragma unroll
                for (int ni = 0; ni < 4; ++ni)
                    mma16816(acc[mi][ni], a[mi], &b[ni >> 1][(ni & 1) * 2]);
        }

        if (++ldSlot == STAGES) ldSlot = 0;
        if (++pfSlot == STAGES) pfSlot = 0;
    }

    // ---- epilogue: direct float2 stores --------------------------------
#pragma unroll
    for (int mi = 0; mi < 4; ++mi) {
#pragma unroll
        for (int h = 0; h < 2; ++h) {
            size_t row = (size_t)(mBase + wm + mi * 16 + h * 8 + (lane >> 2));
            float* p = out + row * N_DIM + nBase + wn + (lane & 3) * 2;
#pragma unroll
            for (int ni = 0; ni < 4; ++ni) {
                float2 v = make_float2(acc[mi][ni][2 * h], acc[mi][ni][2 * h + 1]);
                *reinterpret_cast<float2*>(p + ni * 8) = v;
            }
        }
    }
}

// ---------------------------------------------------------------------------
extern "C" void kernel_launch(void* const* d_in, const int* in_sizes, int n_in,
                              void* d_out, int out_size) {
    const float* x = (const float*)d_in[0];   // [8192, 2048] fp32
    const float* w = (const float*)d_in[1];   // [2048, 2048] fp32
    float* out = (float*)d_out;               // [8192, 2048] fp32

    void *xh_ptr = nullptr, *wb_ptr = nullptr;
    cudaGetSymbolAddress(&xh_ptr, g_Xh);
    cudaGetSymbolAddress(&wb_ptr, g_Wb);

    prep_kernel<<<CONVERT_BLOCKS + BIN_BLOCKS, 256>>>(
        x, w, (__half*)xh_ptr, (__half*)wb_ptr);

    cudaFuncSetAttribute(bingemm_kernel,
                         cudaFuncAttributeMaxDynamicSharedMemorySize, SMEM_TOTAL);
    bingemm_kernel<<<dim3(N_DIM / BN, B_DIM / BM), 256, SMEM_TOTAL>>>(
        (const __half*)xh_ptr, (const __half*)wb_ptr, out);
}

// round 17
// speedup vs baseline: 1.1134x; 1.0820x over previous
#include <cuda_runtime.h>
#include <cuda_fp16.h>
#include <cstdint>

// ============================================================================
// BinaryDense: out[8192,2048] = X[8192,2048] @ (W >= 0 ? 1 : 0)[2048,2048]
// Plain sm_100 target (no tcgen05). fp16 mma.sync HMMA GEMM, fp32 accum.
// R17 = R4 (best measured GEMM: 179.6us, in-loop eta 0.84) + co-resident
// CTA stagger. Evidence: overhead/iter is ~280cyc at 2 CTA/SM vs ~1050 at
// 1 CTA/SM (R16) -> co-residency covers drains. But equal CTAs launched
// together drain in LOCKSTEP; a ~1200cyc one-time delay for the second
// launch-wave (flat-bid/148 odd) anti-phases the pair so each CTA's
// barrier drain overlaps the other's MMA issue.
// ============================================================================

#define B_DIM 8192
#define K_DIM 2048
#define N_DIM 2048

#define BM 128
#define BN 128
#define BK 64
#define STAGES 3
#define KTILES (K_DIM / BK)          // 32

#define A_STAGE_BYTES (BM * BK * 2)  // 16384
#define B_STAGE_BYTES (BN * BK * 2)  // 16384
#define STAGE_BYTES (A_STAGE_BYTES + B_STAGE_BYTES)  // 32768
#define SMEM_TOTAL (STAGES * STAGE_BYTES)            // 98304 (x2 CTA = 192K)

#define CONVERT_BLOCKS 8192          // X: 8192*2048 / (256*8)
#define BIN_BLOCKS (64 * 64)         // W 32x32 tiles

// Scratch: fp16 X and binarized+transposed W (Wb is [N, K], K contiguous)
__device__ __align__(1024) __half g_Xh[(size_t)B_DIM * K_DIM];
__device__ __align__(1024) __half g_Wb[(size_t)N_DIM * K_DIM];

// ---------------------------------------------------------------------------
__device__ __forceinline__ uint32_t smem_u32(const void* p) {
    uint32_t a;
    asm("{ .reg .u64 t; cvta.to.shared.u64 t, %1; cvt.u32.u64 %0, t; }"
        : "=r"(a) : "l"(p));
    return a;
}

__device__ __forceinline__ void cp_async16(uint32_t dst, const void* src) {
    asm volatile("cp.async.cg.shared.global [%0], [%1], 16;"
                 :: "r"(dst), "l"(src) : "memory");
}
__device__ __forceinline__ void cp_commit() {
    asm volatile("cp.async.commit_group;" ::: "memory");
}
template <int N>
__device__ __forceinline__ void cp_wait() {
    asm volatile("cp.async.wait_group %0;" :: "n"(N) : "memory");
}

__device__ __forceinline__ void ldsm_x4(uint32_t& r0, uint32_t& r1,
                                        uint32_t& r2, uint32_t& r3, uint32_t a) {
    asm volatile("ldmatrix.sync.aligned.m8n8.x4.shared.b16 {%0,%1,%2,%3}, [%4];"
                 : "=r"(r0), "=r"(r1), "=r"(r2), "=r"(r3) : "r"(a));
}

__device__ __forceinline__ void mma16816(float* d, const uint32_t* a,
                                         const uint32_t* b) {
    asm volatile(
        "mma.sync.aligned.m16n8k16.row.col.f32.f16.f16.f32 "
        "{%0,%1,%2,%3}, {%4,%5,%6,%7}, {%8,%9}, {%0,%1,%2,%3};"
        : "+f"(d[0]), "+f"(d[1]), "+f"(d[2]), "+f"(d[3])
        : "r"(a[0]), "r"(a[1]), "r"(a[2]), "r"(a[3]), "r"(b[0]), "r"(b[1]));
}

// ---------------------------------------------------------------------------
// Prep kernel (merged): blocks [0, CONVERT_BLOCKS) convert X fp32->fp16;
// blocks [CONVERT_BLOCKS, +BIN_BLOCKS) binarize+transpose W -> Wb[N,K] fp16.
// ---------------------------------------------------------------------------
__global__ void __launch_bounds__(256) prep_kernel(
    const float* __restrict__ x, const float* __restrict__ w,
    __half* __restrict__ xh, __half* __restrict__ wb) {
    int bid = blockIdx.x;
    int tid = threadIdx.x;
    if (bid < CONVERT_BLOCKS) {
        size_t i = ((size_t)bid * 256 + tid) * 8;
        float4 v0 = *reinterpret_cast<const float4*>(x + i);
        float4 v1 = *reinterpret_cast<const float4*>(x + i + 4);
        union { __half2 h[4]; uint4 u; } pk;
        pk.h[0] = __floats2half2_rn(v0.x, v0.y);
        pk.h[1] = __floats2half2_rn(v0.z, v0.w);
        pk.h[2] = __floats2half2_rn(v1.x, v1.y);
        pk.h[3] = __floats2half2_rn(v1.z, v1.w);
        *reinterpret_cast<uint4*>(xh + i) = pk.u;
    } else {
        __shared__ __half tile[32][33];
        int b = bid - CONVERT_BLOCKS;
        int n0 = (b & 63) * 32, k0 = (b >> 6) * 32;
        int tx = tid & 31, ty = tid >> 5;
#pragma unroll
        for (int r = 0; r < 32; r += 8) {
            float v = w[(size_t)(k0 + ty + r) * N_DIM + n0 + tx];
            tile[ty + r][tx] = __float2half(v < 0.0f ? 0.0f : 1.0f);
        }
        __syncthreads();
#pragma unroll
        for (int r = 0; r < 32; r += 8) {
            wb[(size_t)(n0 + ty + r) * K_DIM + k0 + tx] = tile[tx][ty + r];
        }
    }
}

// ---------------------------------------------------------------------------
// GEMM: 128x128 block tile, BK=64, 3-stage cp.async, one __syncthreads per
// iteration, 2 CTAs/SM. 256 threads = 8 warps (2 M x 4 N), 64x32 warp tiles.
// Anti-phase stagger: flat-bid/148 odd CTAs nanosleep ~1200cyc pre-prologue.
// Smem rows 128 B (64 halfs); SW128 swizzle: 16B-chunk ^= (row & 7).
// ---------------------------------------------------------------------------
__global__ void __launch_bounds__(256, 2)
bingemm_kernel(const __half* __restrict__ Xh, const __half* __restrict__ Wb,
               float* __restrict__ out) {
    extern __shared__ char smem[];
    const uint32_t sb = smem_u32(smem);

    const int tid = threadIdx.x;
    const int lane = tid & 31;
    const int wid = tid >> 5;
    const int wm = (wid >> 2) * 64;   // warp M offset (2 rows of warps)
    const int wn = (wid & 3) * 32;    // warp N offset (4 cols of warps)

    const int mBase = blockIdx.y * BM;
    const int nBase = blockIdx.x * BN;

    // ---- anti-phase stagger for the co-resident CTA pair ----------------
    // Classic placement pairs flat bids b and b+148 on one SM. Delay the
    // second launch-wave ~half an iteration so the pair's barrier drains
    // interleave with each other's MMA issue instead of coinciding.
    {
        int flat = blockIdx.x + blockIdx.y * gridDim.x;
        if ((flat / 148) & 1) __nanosleep(600);
    }

    // ---- cp.async precompute: 8 loads/thread/iter (4 A + 4 B) ----------
    const int row0 = tid >> 3;              // 0..31
    const int chunk = tid & 7;
    uint32_t dstA[4], dstB[4];
    const __half* srcA[4];
    const __half* srcB[4];
#pragma unroll
    for (int p = 0; p < 4; ++p) {
        int r = row0 + 32 * p;
        uint32_t sw = (uint32_t)(chunk ^ (r & 7)) * 16;
        dstA[p] = r * 128 + sw;
        dstB[p] = A_STAGE_BYTES + r * 128 + sw;
        srcA[p] = Xh + (size_t)(mBase + r) * K_DIM + chunk * 8;
        srcB[p] = Wb + (size_t)(nBase + r) * K_DIM + chunk * 8;
    }

    // ---- ldmatrix addresses (stage-relative; k16 step s => XOR s<<5) ---
    uint32_t aAddr[4];
#pragma unroll
    for (int mi = 0; mi < 4; ++mi) {
        int r = wm + mi * 16 + (lane & 15);
        int kc0 = lane >> 4;
        aAddr[mi] = (uint32_t)(r * 128 + ((kc0 ^ (r & 7)) * 16));
    }
    uint32_t bAddr[2];
#pragma unroll
    for (int j = 0; j < 2; ++j) {
        int r = wn + j * 16 + (lane & 7) + ((lane >> 4) & 1) * 8;
        int kc0 = (lane >> 3) & 1;
        bAddr[j] = (uint32_t)(A_STAGE_BYTES + r * 128 + ((kc0 ^ (r & 7)) * 16));
    }

    float acc[4][4][4];
#pragma unroll
    for (int mi = 0; mi < 4; ++mi)
#pragma unroll
        for (int ni = 0; ni < 4; ++ni)
#pragma unroll
            for (int e = 0; e < 4; ++e) acc[mi][ni][e] = 0.0f;

    // ---- prologue: fill STAGES-1 = 2 stages ----------------------------
#pragma unroll
    for (int s = 0; s < STAGES - 1; ++s) {
        uint32_t st = sb + s * STAGE_BYTES;
        int kOff = s * BK;
#pragma unroll
        for (int p = 0; p < 4; ++p) {
            cp_async16(st + dstA[p], srcA[p] + kOff);
            cp_async16(st + dstB[p], srcB[p] + kOff);
        }
        cp_commit();
    }

    // ---- mainloop: one __syncthreads per BK=64 iteration ---------------
    int ldSlot = 0, pfSlot = STAGES - 1;
    for (int it = 0; it < KTILES; ++it) {
        cp_wait<STAGES - 2>();   // stage `it` resident (own groups)
        __syncthreads();         // cross-thread completion + stage it-1 free

        int pf = it + STAGES - 1;
        if (pf < KTILES) {       // prefetch into the slot freed by it-1
            uint32_t st = sb + pfSlot * STAGE_BYTES;
            int kOff = pf * BK;
#pragma unroll
            for (int p = 0; p < 4; ++p) {
                cp_async16(st + dstA[p], srcA[p] + kOff);
                cp_async16(st + dstB[p], srcB[p] + kOff);
            }
        }
        cp_commit();

        uint32_t stage = sb + ldSlot * STAGE_BYTES;
#pragma unroll
        for (int s = 0; s < 4; ++s) {       // four k16 steps per BK=64
            const uint32_t kx = (uint32_t)s << 5;   // XOR: chunk bits 1-2
            uint32_t a[4][4];
#pragma unroll
            for (int mi = 0; mi < 4; ++mi)
                ldsm_x4(a[mi][0], a[mi][1], a[mi][2], a[mi][3],
                        stage + (aAddr[mi] ^ kx));
            uint32_t b[2][4];
#pragma unroll
            for (int j = 0; j < 2; ++j)
                ldsm_x4(b[j][0], b[j][1], b[j][2], b[j][3],
                        stage + (bAddr[j] ^ kx));
#pragma unroll
            for (int mi = 0; mi < 4; ++mi)
#pragma unroll
                for (int ni = 0; ni < 4; ++ni)
                    mma16816(acc[mi][ni], a[mi], &b[ni >> 1][(ni & 1) * 2]);
        }

        if (++ldSlot == STAGES) ldSlot = 0;
        if (++pfSlot == STAGES) pfSlot = 0;
    }

    // ---- epilogue: direct float2 stores --------------------------------
#pragma unroll
    for (int mi = 0; mi < 4; ++mi) {
#pragma unroll
        for (int h = 0; h < 2; ++h) {
            size_t row = (size_t)(mBase + wm + mi * 16 + h * 8 + (lane >> 2));
            float* p = out + row * N_DIM + nBase + wn + (lane & 3) * 2;
#pragma unroll
            for (int ni = 0; ni < 4; ++ni) {
                float2 v = make_float2(acc[mi][ni][2 * h], acc[mi][ni][2 * h + 1]);
                *reinterpret_cast<float2*>(p + ni * 8) = v;
            }
        }
    }
}

// ---------------------------------------------------------------------------
extern "C" void kernel_launch(void* const* d_in, const int* in_sizes, int n_in,
                              void* d_out, int out_size) {
    const float* x = (const float*)d_in[0];   // [8192, 2048] fp32
    const float* w = (const float*)d_in[1];   // [2048, 2048] fp32
    float* out = (float*)d_out;               // [8192, 2048] fp32

    void *xh_ptr = nullptr, *wb_ptr = nullptr;
    cudaGetSymbolAddress(&xh_ptr, g_Xh);
    cudaGetSymbolAddress(&wb_ptr, g_Wb);

    prep_kernel<<<CONVERT_BLOCKS + BIN_BLOCKS, 256>>>(
        x, w, (__half*)xh_ptr, (__half*)wb_ptr);

    cudaFuncSetAttribute(bingemm_kernel,
                         cudaFuncAttributeMaxDynamicSharedMemorySize, SMEM_TOTAL);
    bingemm_kernel<<<dim3(N_DIM / BN, B_DIM / BM), 256, SMEM_TOTAL>>>(
        (const __half*)xh_ptr, (const __half*)wb_ptr, out);
}